// round 1
// baseline (speedup 1.0000x reference)
#include <cuda_runtime.h>

// 3-layer LSTM (IN=5, H=50) + FC(50->1), B=1024, T=512.
// Fully fused persistent kernel: one block per batch chunk keeps all weights
// (200KB) and all recurrent state in shared memory; runs all 3 layers for all
// 512 timesteps. Zero inter-layer global traffic.
//
// Gate math uses Blackwell packed fp32 FMA (fma.rn.f32x2): each of 200 gate
// threads holds the running dot for 7 batch elements (7 independent FMA chains).
// Weights live in shared, transposed to [k-quad][gate] float4 so the per-thread
// weight load is a conflict-free LDS.128 and the input-vector load is a
// broadcast (all threads same address).

#define T_STEPS   512
#define IN_DIM    5
#define HID       50
#define G4        200           // 4*HID gate rows
#define NB        7             // max batch elems per block
#define NTHREADS  256
#define GRID      148

// Shared memory layout (float offsets)
enum {
    W1_OFF = 0,                 // 14 kq * 200 g * 4 = 11200   (row = [Wih1(5), 0, Whh1(50)] len 56)
    W2_OFF = 11200,             // 25 kq * 200 g * 4 = 20000   (row = [Wih2(50), Whh2(50)] len 100)
    W3_OFF = 31200,             // 20000
    BS_OFF = 51200,             // 3 * 200 combined biases
    V1_OFF = 51800,             // NB * 56   : [x_t(5), pad, h1(50)]
    V2_OFF = 52192,             // NB * 100  : [h1(50), h2(50)]
    V3_OFF = 52892,             // NB * 100  : [h2(50), h3(50)]
    C_OFF  = 53592,             // 3 * NB * 50 cell states
    GT_OFF = 54642,             // NB * 200 activated gates
    SH_FLOATS = 56042           // 224168 bytes
};

__device__ __forceinline__ unsigned long long ffma2(unsigned long long a,
                                                    unsigned long long b,
                                                    unsigned long long c) {
    unsigned long long d;
    asm("fma.rn.f32x2 %0, %1, %2, %3;" : "=l"(d) : "l"(a), "l"(b), "l"(c));
    return d;
}

__device__ __forceinline__ float fast_ex2(float x) {
    float y; asm("ex2.approx.ftz.f32 %0, %1;" : "=f"(y) : "f"(x)); return y;
}
__device__ __forceinline__ float fast_rcp(float x) {
    float y; asm("rcp.approx.ftz.f32 %0, %1;" : "=f"(y) : "f"(x)); return y;
}
// accurate tanh via ex2+rcp: tanh(x) = 2/(1+exp(-2x)) - 1
__device__ __forceinline__ float tanh_acc(float x) {
    float r = fast_rcp(1.0f + fast_ex2(-2.8853900817779268f * x));
    return r + r - 1.0f;
}

// Compute all 200 gate pre-activations + activations for NB batch elems.
// g = this thread's gate row (0..199). KQ = number of float4 chunks in the
// combined [input, h] vector; VS = stride of the v array per batch elem.
template<int KQ, int VS>
__device__ __forceinline__ void gates_phase(float* sh, int woff, int voff,
                                            int bsoff, int g) {
    const ulonglong2* wp = reinterpret_cast<const ulonglong2*>(sh + woff);
    unsigned long long acc[NB];
    float bz = sh[bsoff + g];
    unsigned long long ini;
    asm("mov.b64 %0, {%1, %2};" : "=l"(ini) : "f"(bz), "f"(0.0f));
#pragma unroll
    for (int b = 0; b < NB; b++) acc[b] = ini;

#pragma unroll 2
    for (int kq = 0; kq < KQ; kq++) {
        ulonglong2 w = wp[kq * G4 + g];            // LDS.128, stride-1 across threads
#pragma unroll
        for (int b = 0; b < NB; b++) {
            ulonglong2 v = *reinterpret_cast<const ulonglong2*>(
                sh + voff + b * VS + kq * 4);      // broadcast LDS.128
            acc[b] = ffma2(w.x, v.x, acc[b]);
            acc[b] = ffma2(w.y, v.y, acc[b]);
        }
    }

    bool ist = (g >= 2 * HID) && (g < 3 * HID);    // tanh gate range
#pragma unroll
    for (int b = 0; b < NB; b++) {
        float lo, hi;
        asm("mov.b64 {%0, %1}, %2;" : "=f"(lo), "=f"(hi) : "l"(acc[b]));
        float xv = lo + hi;
        float xs = ist ? xv + xv : xv;
        float r = fast_rcp(1.0f + fast_ex2(-1.4426950408889634f * xs));
        sh[GT_OFF + b * G4 + g] = ist ? (r + r - 1.0f) : r;
    }
}

// c/h update for one layer: 350 tasks (NB*HID) spread over the block.
__device__ __forceinline__ void update_phase(float* sh, int tid, int coff,
                                             int d1, int s1,
                                             int d2, int s2, bool has2) {
    for (int task = tid; task < NB * HID; task += NTHREADS) {
        int b = task / HID;
        int j = task - b * HID;
        const float* gp = sh + GT_OFF + b * G4 + j;
        float iv = gp[0];
        float fv = gp[HID];
        float gv = gp[2 * HID];
        float ov = gp[3 * HID];
        int ci = coff + b * HID + j;
        float cn = fv * sh[ci] + iv * gv;
        sh[ci] = cn;
        float h = ov * tanh_acc(cn);
        sh[d1 + b * s1 + j] = h;
        if (has2) sh[d2 + b * s2 + j] = h;
    }
}

__global__ void __launch_bounds__(NTHREADS, 1)
lstm3_fused_kernel(const float* __restrict__ x,
                   const float* __restrict__ Wih1, const float* __restrict__ Whh1,
                   const float* __restrict__ bih1, const float* __restrict__ bhh1,
                   const float* __restrict__ Wih2, const float* __restrict__ Whh2,
                   const float* __restrict__ bih2, const float* __restrict__ bhh2,
                   const float* __restrict__ Wih3, const float* __restrict__ Whh3,
                   const float* __restrict__ bih3, const float* __restrict__ bhh3,
                   const float* __restrict__ fcW, const float* __restrict__ fcb,
                   float* __restrict__ out) {
    extern __shared__ float sh[];
    const int tid = threadIdx.x;
    const int bid = blockIdx.x;

    // batch partition: 136 blocks * 7 + 12 blocks * 6 = 1024
    int b0, cnt;
    if (bid < 136) { b0 = bid * 7;                cnt = 7; }
    else           { b0 = 952 + (bid - 136) * 6;  cnt = 6; }

    // zero all recurrent state (v1, v2, v3, c)
    for (int i = V1_OFF + tid; i < GT_OFF; i += NTHREADS) sh[i] = 0.0f;

    // stage weights into shared, transposed to [kq][g] float4 layout
    for (int idx = tid; idx < G4 * 56; idx += NTHREADS) {
        int g = idx / 56, k = idx - g * 56;
        float v;
        if (k < IN_DIM)        v = Wih1[g * IN_DIM + k];
        else if (k == IN_DIM)  v = 0.0f;
        else                   v = Whh1[g * HID + (k - 6)];
        sh[W1_OFF + (k >> 2) * (G4 * 4) + g * 4 + (k & 3)] = v;
    }
    for (int idx = tid; idx < G4 * 100; idx += NTHREADS) {
        int g = idx / 100, k = idx - g * 100;
        float v = (k < HID) ? Wih2[g * HID + k] : Whh2[g * HID + (k - HID)];
        sh[W2_OFF + (k >> 2) * (G4 * 4) + g * 4 + (k & 3)] = v;
    }
    for (int idx = tid; idx < G4 * 100; idx += NTHREADS) {
        int g = idx / 100, k = idx - g * 100;
        float v = (k < HID) ? Wih3[g * HID + k] : Whh3[g * HID + (k - HID)];
        sh[W3_OFF + (k >> 2) * (G4 * 4) + g * 4 + (k & 3)] = v;
    }
    for (int idx = tid; idx < 3 * G4; idx += NTHREADS) {
        int l = idx / G4, g = idx - l * G4;
        const float* bi = (l == 0) ? bih1 : (l == 1) ? bih2 : bih3;
        const float* bh = (l == 0) ? bhh1 : (l == 1) ? bhh2 : bhh3;
        sh[BS_OFF + idx] = bi[g] + bh[g];
    }
    // x for t=0
    if (tid < NB * IN_DIM) {
        int b = tid / IN_DIM, d = tid - b * IN_DIM;
        if (b < cnt)
            sh[V1_OFF + b * 56 + d] =
                x[(size_t)(b0 + b) * T_STEPS * IN_DIM + d];
    }
    __syncthreads();

    for (int t = 0; t < T_STEPS; t++) {
        // spare threads prefetch x_{t+1} into registers (LDG overlaps phase 1)
        float xpre = 0.0f; int pb = 0, pd = 0; bool pvalid = false;
        if (tid >= G4 && tid < G4 + NB * IN_DIM) {
            int i = tid - G4;
            pb = i / IN_DIM; pd = i - pb * IN_DIM;
            pvalid = (t + 1 < T_STEPS) && (pb < cnt);
            if (pvalid)
                xpre = x[(size_t)(b0 + pb) * T_STEPS * IN_DIM
                         + (t + 1) * IN_DIM + pd];
        }

        // layer 1 gates: v1 = [x_t, pad, h1]
        if (tid < G4) gates_phase<14, 56>(sh, W1_OFF, V1_OFF, BS_OFF, tid);
        __syncthreads();
        // h1/c1 update -> v1 h-slot and v2 x-slot
        update_phase(sh, tid, C_OFF, V1_OFF + 6, 56, V2_OFF, 100, true);
        __syncthreads();

        // layer 2 gates: v2 = [h1_new, h2_prev]; spare threads commit x_{t+1}
        if (tid < G4) gates_phase<25, 100>(sh, W2_OFF, V2_OFF, BS_OFF + G4, tid);
        else if (pvalid) sh[V1_OFF + pb * 56 + pd] = xpre;
        __syncthreads();
        update_phase(sh, tid, C_OFF + NB * HID, V2_OFF + HID, 100, V3_OFF, 100, true);
        __syncthreads();

        // layer 3 gates: v3 = [h2_new, h3_prev]
        if (tid < G4) gates_phase<25, 100>(sh, W3_OFF, V3_OFF, BS_OFF + 2 * G4, tid);
        __syncthreads();
        update_phase(sh, tid, C_OFF + 2 * NB * HID, V3_OFF + HID, 100, 0, 0, false);
        __syncthreads();
    }

    // final FC on h3 at t = T-1 (OUT = 1)
    if (tid < cnt) {
        float a = fcb[0];
#pragma unroll
        for (int j = 0; j < HID; j++)
            a += fcW[j] * sh[V3_OFF + tid * 100 + HID + j];
        out[b0 + tid] = a;
    }
}

extern "C" void kernel_launch(void* const* d_in, const int* in_sizes, int n_in,
                              void* d_out, int out_size) {
    const float* x    = (const float*)d_in[0];
    const float* Wih1 = (const float*)d_in[1];
    const float* Whh1 = (const float*)d_in[2];
    const float* bih1 = (const float*)d_in[3];
    const float* bhh1 = (const float*)d_in[4];
    const float* Wih2 = (const float*)d_in[5];
    const float* Whh2 = (const float*)d_in[6];
    const float* bih2 = (const float*)d_in[7];
    const float* bhh2 = (const float*)d_in[8];
    const float* Wih3 = (const float*)d_in[9];
    const float* Whh3 = (const float*)d_in[10];
    const float* bih3 = (const float*)d_in[11];
    const float* bhh3 = (const float*)d_in[12];
    const float* fcW  = (const float*)d_in[13];
    const float* fcb  = (const float*)d_in[14];

    size_t shbytes = (size_t)SH_FLOATS * sizeof(float);
    cudaFuncSetAttribute(lstm3_fused_kernel,
                         cudaFuncAttributeMaxDynamicSharedMemorySize,
                         (int)shbytes);
    lstm3_fused_kernel<<<GRID, NTHREADS, shbytes>>>(
        x, Wih1, Whh1, bih1, bhh1, Wih2, Whh2, bih2, bhh2,
        Wih3, Whh3, bih3, bhh3, fcW, fcb, (float*)d_out);
}